// round 2
// baseline (speedup 1.0000x reference)
#include <cuda_runtime.h>
#include <cuda_bf16.h>

// Problem constants
#define VOCAB 10000
#define HID   256
#define BATCH 32
#define SEQL  512

// ---------------- scratch: y[seq*batch, hid] (16 MB) ----------------
__device__ float g_y[(size_t)SEQL * BATCH * HID];

// ---------------- Recurrence kernel ----------------
// One CTA per batch element (32 CTAs, 256 threads). Thread i computes h[i].
// Whh column i: rows [0,KREG) live in registers, rows [KREG,256) live in
// shared memory, stored as [kq][i] float4 so each thread's read is a
// conflict-free LDS.128 (lane i reads 16B at offset i*16 within a kq slab).
#define KREG 128
#define KSH  (HID - KREG)   // 128
#define KSHQ (KSH / 4)      // 32
#define RNN_SMEM (KSHQ * HID * 16)  // 131072 bytes

__global__ void __launch_bounds__(256, 1)
rnn_kernel(const int* __restrict__ tokens, const float* __restrict__ state,
           const float* __restrict__ Wxh, const float* __restrict__ Whh,
           const float* __restrict__ bh, float* __restrict__ hfin)
{
    extern __shared__ float4 Wsh4[];                 // [KSHQ][HID]
    __shared__ __align__(16) float hbuf[2][HID];

    const int b = blockIdx.x;
    const int i = threadIdx.x;

    // Register-resident Whh rows 0..KREG-1 (column i)
    float Wreg[KREG];
#pragma unroll
    for (int k = 0; k < KREG; k++)
        Wreg[k] = Whh[k * HID + i];

    // Shared-resident Whh rows KREG..255, packed 4 k's per float4
    for (int kq = 0; kq < KSHQ; kq++) {
        float4 v;
        v.x = Whh[(KREG + 4 * kq + 0) * HID + i];
        v.y = Whh[(KREG + 4 * kq + 1) * HID + i];
        v.z = Whh[(KREG + 4 * kq + 2) * HID + i];
        v.w = Whh[(KREG + 4 * kq + 3) * HID + i];
        Wsh4[kq * HID + i] = v;
    }

    const float bias = bh[i];
    hbuf[0][i] = state[b * HID + i];
    __syncthreads();

    const int* toks = tokens + b * SEQL;
    float e = Wxh[toks[0] * HID + i];   // embedding row for t=0
    int cur = 0;

    for (int t = 0; t < SEQL; t++) {
        // prefetch next embedding row (hides L2/DRAM latency under the dot)
        float e_next = (t + 1 < SEQL) ? Wxh[toks[t + 1] * HID + i] : 0.f;

        float acc = e + bias;
        const float4* h4 = (const float4*)hbuf[cur];

        // register part
#pragma unroll
        for (int kq = 0; kq < KREG / 4; kq++) {
            float4 hv = h4[kq];
            acc = fmaf(hv.x, Wreg[4 * kq + 0], acc);
            acc = fmaf(hv.y, Wreg[4 * kq + 1], acc);
            acc = fmaf(hv.z, Wreg[4 * kq + 2], acc);
            acc = fmaf(hv.w, Wreg[4 * kq + 3], acc);
        }
        // shared part
#pragma unroll
        for (int kq = 0; kq < KSHQ; kq++) {
            float4 hv = h4[KREG / 4 + kq];
            float4 wv = Wsh4[kq * HID + i];
            acc = fmaf(hv.x, wv.x, acc);
            acc = fmaf(hv.y, wv.y, acc);
            acc = fmaf(hv.z, wv.z, acc);
            acc = fmaf(hv.w, wv.w, acc);
        }

        float hn = tanhf(acc);
        g_y[((size_t)t * BATCH + b) * HID + i] = hn;
        hbuf[cur ^ 1][i] = hn;
        if (t == SEQL - 1) hfin[b * HID + i] = hn;
        __syncthreads();
        cur ^= 1;
        e = e_next;
    }
}

// ---------------- Output GEMM: C = Y @ Wd + bd ----------------
// M=16384, N=10000, K=256. 128x128 block tile, BK=16, 256 threads,
// 8x8 per-thread micro-tile with packed f32x2 FMAs (Blackwell sm_100+).
// Packed pairs are carried as unsigned long long (asm 'l' constraint is
// 64-bit integer; the f32x2 pipe only sees the bit pattern).
#define BM 128
#define BN 128
#define BK 16

typedef unsigned long long u64;

__device__ __forceinline__ u64 pack2(float a) {
    u64 d;
    asm("mov.b64 %0, {%1, %1};" : "=l"(d) : "f"(a));
    return d;
}
__device__ __forceinline__ void unpack2(u64 d, float& lo, float& hi) {
    asm("mov.b64 {%0, %1}, %2;" : "=f"(lo), "=f"(hi) : "l"(d));
}

__global__ void __launch_bounds__(256, 2)
gemm_kernel(const float* __restrict__ B, const float* __restrict__ bd,
            float* __restrict__ C)
{
    const int N = VOCAB;          // 10000
    const int K = HID;            // 256

    __shared__ __align__(16) float As[BK][BM];
    __shared__ __align__(16) float Bs[BK][BN];

    const int tid = threadIdx.x;
    const int m0 = blockIdx.y * BM;
    const int n0 = blockIdx.x * BN;
    const int tx = tid & 15;      // 0..15 -> 8 cols each
    const int ty = tid >> 4;      // 0..15 -> 8 rows each

    u64 acc[8][4];                // 8 rows x 4 packed col-pairs
#pragma unroll
    for (int ii = 0; ii < 8; ii++)
#pragma unroll
        for (int jj = 0; jj < 4; jj++)
            acc[ii][jj] = 0ull;   // bits == two 0.0f floats

    for (int k0 = 0; k0 < K; k0 += BK) {
        // load A tile [BM x BK] from g_y, store transposed As[k][m]
#pragma unroll
        for (int q = 0; q < 2; q++) {
            int f = tid + q * 256;
            int r = f >> 2, c = f & 3;
            float4 v = *(const float4*)(g_y + (size_t)(m0 + r) * K + k0 + c * 4);
            As[c * 4 + 0][r] = v.x;
            As[c * 4 + 1][r] = v.y;
            As[c * 4 + 2][r] = v.z;
            As[c * 4 + 3][r] = v.w;
        }
        // load B tile [BK x BN] (guard partial N tile; N%4==0 so float4-safe)
#pragma unroll
        for (int q = 0; q < 2; q++) {
            int f = tid + q * 256;
            int r = f >> 5, c = f & 31;
            int col = n0 + c * 4;
            float4 v = (col < N)
                ? *(const float4*)(B + (size_t)(k0 + r) * N + col)
                : make_float4(0.f, 0.f, 0.f, 0.f);
            *(float4*)&Bs[r][c * 4] = v;
        }
        __syncthreads();

#pragma unroll
        for (int k = 0; k < BK; k++) {
            float4 a0 = *(const float4*)&As[k][ty * 8];
            float4 a1 = *(const float4*)&As[k][ty * 8 + 4];
            const u64* Bd = (const u64*)&Bs[k][tx * 8];
            u64 b0 = Bd[0], b1 = Bd[1], b2 = Bd[2], b3 = Bd[3];
            float a[8] = {a0.x, a0.y, a0.z, a0.w, a1.x, a1.y, a1.z, a1.w};
#pragma unroll
            for (int ii = 0; ii < 8; ii++) {
                u64 ad = pack2(a[ii]);
                asm("fma.rn.f32x2 %0, %1, %2, %0;" : "+l"(acc[ii][0]) : "l"(ad), "l"(b0));
                asm("fma.rn.f32x2 %0, %1, %2, %0;" : "+l"(acc[ii][1]) : "l"(ad), "l"(b1));
                asm("fma.rn.f32x2 %0, %1, %2, %0;" : "+l"(acc[ii][2]) : "l"(ad), "l"(b2));
                asm("fma.rn.f32x2 %0, %1, %2, %0;" : "+l"(acc[ii][3]) : "l"(ad), "l"(b3));
            }
        }
        __syncthreads();
    }

    // epilogue: add bias, store (N is even, cols here are even -> pair-safe)
#pragma unroll
    for (int ii = 0; ii < 8; ii++) {
        size_t row = (size_t)(m0 + ty * 8 + ii);
#pragma unroll
        for (int jj = 0; jj < 4; jj++) {
            int col = n0 + tx * 8 + jj * 2;
            if (col < N) {
                float lo, hi;
                unpack2(acc[ii][jj], lo, hi);
                float2 out;
                out.x = lo + bd[col];
                out.y = hi + bd[col + 1];
                *(float2*)&C[row * N + col] = out;
            }
        }
    }
}

// ---------------- launcher ----------------
extern "C" void kernel_launch(void* const* d_in, const int* in_sizes, int n_in,
                              void* d_out, int out_size)
{
    const int*   tokens = (const int*)  d_in[0];  // [32, 512] int32
    const float* state  = (const float*)d_in[1];  // [32, 256]
    const float* Wxh    = (const float*)d_in[2];  // [10000, 256]
    const float* Whh    = (const float*)d_in[3];  // [256, 256]
    const float* bh     = (const float*)d_in[4];  // [256]
    const float* Wd     = (const float*)d_in[5];  // [256, 10000]
    const float* bd     = (const float*)d_in[6];  // [10000]

    float* out  = (float*)d_out;                         // [16384, 10000]
    float* hfin = out + (size_t)SEQL * BATCH * VOCAB;    // [32, 256]

    // opt-in to >48KB dynamic smem (idempotent, not a graph node, no alloc)
    cudaFuncSetAttribute(rnn_kernel,
                         cudaFuncAttributeMaxDynamicSharedMemorySize, RNN_SMEM);

    rnn_kernel<<<BATCH, 256, RNN_SMEM>>>(tokens, state, Wxh, Whh, bh, hfin);

    dim3 grid((VOCAB + BN - 1) / BN, (SEQL * BATCH) / BM);   // (79, 128)
    gemm_kernel<<<grid, 256>>>(Wd, bd, out);
}

// round 5
// speedup vs baseline: 1.9581x; 1.9581x over previous
#include <cuda_runtime.h>
#include <cuda_bf16.h>
#include <cstdint>

// Problem constants
#define VOCAB 10000
#define HID   256
#define BATCH 32
#define SEQL  512
#define MTOT  (SEQL * BATCH)   // 16384

// ---------------- scratch (bf16 split operands) ----------------
__device__ __nv_bfloat16 g_yh[(size_t)MTOT * HID];    // Y hi  [M, K]
__device__ __nv_bfloat16 g_yl[(size_t)MTOT * HID];    // Y lo  [M, K]
__device__ __nv_bfloat16 g_wth[(size_t)VOCAB * HID];  // Wd^T hi [N, K]
__device__ __nv_bfloat16 g_wtl[(size_t)VOCAB * HID];  // Wd^T lo [N, K]

// ================= helpers =================
__device__ __forceinline__ uint32_t smem_u32(const void* p) {
    uint32_t a;
    asm("{ .reg .u64 t; cvta.to.shared.u64 t, %1; cvt.u32.u64 %0, t; }"
        : "=r"(a) : "l"(p));
    return a;
}
__device__ __forceinline__ void cpa16(uint32_t dst, const void* src, uint32_t sz) {
    asm volatile("cp.async.cg.shared.global [%0], [%1], 16, %2;"
                 :: "r"(dst), "l"(src), "r"(sz) : "memory");
}
__device__ __forceinline__ void ldm_x4(uint32_t* r, uint32_t addr) {
    asm volatile("ldmatrix.sync.aligned.m8n8.x4.shared.b16 {%0,%1,%2,%3}, [%4];"
                 : "=r"(r[0]), "=r"(r[1]), "=r"(r[2]), "=r"(r[3]) : "r"(addr));
}
__device__ __forceinline__ void mma_bf16(float* c, const uint32_t* a, const uint32_t* b) {
    asm volatile(
        "mma.sync.aligned.m16n8k16.row.col.f32.bf16.bf16.f32 "
        "{%0,%1,%2,%3}, {%4,%5,%6,%7}, {%8,%9}, {%0,%1,%2,%3};"
        : "+f"(c[0]), "+f"(c[1]), "+f"(c[2]), "+f"(c[3])
        : "r"(a[0]), "r"(a[1]), "r"(a[2]), "r"(a[3]), "r"(b[0]), "r"(b[1]));
}

// ---------------- Recurrence kernel (bf16 split outputs) ----
#define KREG 128
#define KSH  (HID - KREG)
#define KSHQ (KSH / 4)
#define RNN_SMEM (KSHQ * HID * 16)

__global__ void __launch_bounds__(256, 1)
rnn_kernel(const int* __restrict__ tokens, const float* __restrict__ state,
           const float* __restrict__ Wxh, const float* __restrict__ Whh,
           const float* __restrict__ bh, float* __restrict__ hfin)
{
    extern __shared__ float4 Wsh4[];
    __shared__ __align__(16) float hbuf[2][HID];

    const int b = blockIdx.x;
    const int i = threadIdx.x;

    float Wreg[KREG];
#pragma unroll
    for (int k = 0; k < KREG; k++)
        Wreg[k] = Whh[k * HID + i];

    for (int kq = 0; kq < KSHQ; kq++) {
        float4 v;
        v.x = Whh[(KREG + 4 * kq + 0) * HID + i];
        v.y = Whh[(KREG + 4 * kq + 1) * HID + i];
        v.z = Whh[(KREG + 4 * kq + 2) * HID + i];
        v.w = Whh[(KREG + 4 * kq + 3) * HID + i];
        Wsh4[kq * HID + i] = v;
    }

    const float bias = bh[i];
    hbuf[0][i] = state[b * HID + i];
    __syncthreads();

    const int* toks = tokens + b * SEQL;
    float e = Wxh[toks[0] * HID + i];
    int cur = 0;

    for (int t = 0; t < SEQL; t++) {
        float e_next = (t + 1 < SEQL) ? Wxh[toks[t + 1] * HID + i] : 0.f;

        float acc = e + bias;
        const float4* h4 = (const float4*)hbuf[cur];

#pragma unroll
        for (int kq = 0; kq < KREG / 4; kq++) {
            float4 hv = h4[kq];
            acc = fmaf(hv.x, Wreg[4 * kq + 0], acc);
            acc = fmaf(hv.y, Wreg[4 * kq + 1], acc);
            acc = fmaf(hv.z, Wreg[4 * kq + 2], acc);
            acc = fmaf(hv.w, Wreg[4 * kq + 3], acc);
        }
#pragma unroll
        for (int kq = 0; kq < KSHQ; kq++) {
            float4 hv = h4[KREG / 4 + kq];
            float4 wv = Wsh4[kq * HID + i];
            acc = fmaf(hv.x, wv.x, acc);
            acc = fmaf(hv.y, wv.y, acc);
            acc = fmaf(hv.z, wv.z, acc);
            acc = fmaf(hv.w, wv.w, acc);
        }

        float hn = tanhf(acc);
        size_t oidx = ((size_t)t * BATCH + b) * HID + i;
        __nv_bfloat16 hh = __float2bfloat16(hn);
        g_yh[oidx] = hh;
        g_yl[oidx] = __float2bfloat16(hn - __bfloat162float(hh));
        hbuf[cur ^ 1][i] = hn;
        if (t == SEQL - 1) hfin[b * HID + i] = hn;
        __syncthreads();
        cur ^= 1;
        e = e_next;
    }
}

// ---------------- Wd transpose + bf16 split: [K,N] f32 -> [N,K] bf16 hi/lo --
__global__ void __launch_bounds__(256)
wd_transpose_split(const float* __restrict__ Wd)
{
    __shared__ float tile[32][33];
    const int tx = threadIdx.x;          // 0..31
    const int ty = threadIdx.y;          // 0..7
    const int n0 = blockIdx.x * 32;
    const int k0 = blockIdx.y * 32;

#pragma unroll
    for (int r = 0; r < 4; r++) {
        int k = k0 + ty + r * 8;
        int n = n0 + tx;
        tile[ty + r * 8][tx] = (n < VOCAB) ? Wd[(size_t)k * VOCAB + n] : 0.f;
    }
    __syncthreads();

#pragma unroll
    for (int r = 0; r < 4; r++) {
        int n = n0 + ty + r * 8;
        int k = k0 + tx;
        if (n < VOCAB) {
            float v = tile[tx][ty + r * 8];
            __nv_bfloat16 hi = __float2bfloat16(v);
            g_wth[(size_t)n * HID + k] = hi;
            g_wtl[(size_t)n * HID + k] = __float2bfloat16(v - __bfloat162float(hi));
        }
    }
}

// ---------------- mma.sync GEMM: C = (Yh+Yl) @ (Wth+Wtl)^T + bd --------------
// 128x128 CTA tile, 8 warps (2x4), 64x32 per warp. K chunks of 32 bf16,
// double-buffered cp.async. 3-pass bf16 split into shared fp32 accumulators.
// B is [N,K] K-contiguous -> B fragments load with NON-trans ldmatrix
// (lane l gets B[n=l/4][k=(l%4)*2..+1], exactly mma's col-major B layout).
#define GBM 128
#define GBN 128
#define GBK 32
#define ROWB 80                            // bytes per smem row (32 bf16 + pad)
#define MATB (128 * ROWB)                  // 10240 B per matrix tile
#define STAGEB (4 * MATB)                  // Ah, Al, Bh, Bl
#define GSMEM (2 * STAGEB)                 // 81920 B

__global__ void __launch_bounds__(256, 2)
gemm_mma(const __nv_bfloat16* __restrict__ Yh, const __nv_bfloat16* __restrict__ Yl,
         const __nv_bfloat16* __restrict__ Bth, const __nv_bfloat16* __restrict__ Btl,
         const float* __restrict__ bd, float* __restrict__ C)
{
    extern __shared__ __align__(16) char smraw[];
    const uint32_t base = smem_u32(smraw);

    const int tid  = threadIdx.x;
    const int lane = tid & 31;
    const int wid  = tid >> 5;
    const int wm   = wid & 1;              // 0..1
    const int wn   = wid >> 1;             // 0..3
    const int m0   = blockIdx.y * GBM;
    const int n0   = blockIdx.x * GBN;

    float acc[4][4][4];
#pragma unroll
    for (int i = 0; i < 4; i++)
#pragma unroll
        for (int j = 0; j < 4; j++)
#pragma unroll
            for (int q = 0; q < 4; q++)
                acc[i][j][q] = 0.f;

    // ---- stage loader: 8 cp.async.16B per thread ----
    auto load_stage = [&](int st, int kc) {
        const uint32_t sb = base + st * STAGEB;
        const int kel = kc * GBK;
#pragma unroll
        for (int j = 0; j < 2; j++) {
            int u = tid + j * 256;
            int r = u >> 2;
            int sg = u & 3;
            uint32_t off = (uint32_t)r * ROWB + sg * 16;
            cpa16(sb + 0 * MATB + off, Yh + (size_t)(m0 + r) * HID + kel + sg * 8, 16);
            cpa16(sb + 1 * MATB + off, Yl + (size_t)(m0 + r) * HID + kel + sg * 8, 16);
            int nr = n0 + r;
            uint32_t ok = (nr < VOCAB) ? 16u : 0u;
            size_t br = (nr < VOCAB) ? (size_t)nr : 0;
            cpa16(sb + 2 * MATB + off, Bth + br * HID + kel + sg * 8, ok);
            cpa16(sb + 3 * MATB + off, Btl + br * HID + kel + sg * 8, ok);
        }
        asm volatile("cp.async.commit_group;" ::: "memory");
    };

    load_stage(0, 0);

    const int NKC = HID / GBK;             // 8 chunks
    for (int kc = 0; kc < NKC; kc++) {
        if (kc + 1 < NKC) {
            load_stage((kc + 1) & 1, kc + 1);
            asm volatile("cp.async.wait_group 1;" ::: "memory");
        } else {
            asm volatile("cp.async.wait_group 0;" ::: "memory");
        }
        __syncthreads();

        const uint32_t sb = base + (kc & 1) * STAGEB;
        const uint32_t Ah = sb, Al = sb + MATB, Bh = sb + 2 * MATB, Bl = sb + 3 * MATB;

#pragma unroll
        for (int ks = 0; ks < 2; ks++) {
            const int k0 = ks * 16;
            // B fragments: 2 x ldmatrix.x4 (NON-trans) per matrix (n32 x k16)
            uint32_t bh[2][4], bl[2][4];
#pragma unroll
            for (int h = 0; h < 2; h++) {
                int row = wn * 32 + h * 16 + ((lane >> 4) & 1) * 8 + (lane & 7);
                int col = k0 + ((lane >> 3) & 1) * 8;
                uint32_t off = (uint32_t)row * ROWB + col * 2;
                ldm_x4(bh[h], Bh + off);
                ldm_x4(bl[h], Bl + off);
            }
#pragma unroll
            for (int mi = 0; mi < 4; mi++) {
                int rowA = wm * 64 + mi * 16 + (lane & 15);
                int colA = k0 + (lane >> 4) * 8;
                uint32_t offA = (uint32_t)rowA * ROWB + colA * 2;
                uint32_t ah[4], al[4];
                ldm_x4(ah, Ah + offA);
                ldm_x4(al, Al + offA);
#pragma unroll
                for (int ni = 0; ni < 4; ni++) {
                    const uint32_t* ph = &bh[ni >> 1][(ni & 1) * 2];
                    const uint32_t* pl = &bl[ni >> 1][(ni & 1) * 2];
                    mma_bf16(acc[mi][ni], ah, ph);   // Ah * Bh
                    mma_bf16(acc[mi][ni], ah, pl);   // Ah * Bl
                    mma_bf16(acc[mi][ni], al, ph);   // Al * Bh
                }
            }
        }
        __syncthreads();
    }

    // ---- epilogue: bias + store ----
    const int g  = lane >> 2;
    const int tq = lane & 3;
#pragma unroll
    for (int mi = 0; mi < 4; mi++) {
        int r0 = m0 + wm * 64 + mi * 16 + g;
#pragma unroll
        for (int ni = 0; ni < 4; ni++) {
            int col = n0 + wn * 32 + ni * 8 + tq * 2;
            if (col < VOCAB) {
                float b0 = bd[col], b1 = bd[col + 1];
                float2 v0 = { acc[mi][ni][0] + b0, acc[mi][ni][1] + b1 };
                float2 v1 = { acc[mi][ni][2] + b0, acc[mi][ni][3] + b1 };
                *(float2*)(C + (size_t)r0 * VOCAB + col) = v0;
                *(float2*)(C + (size_t)(r0 + 8) * VOCAB + col) = v1;
            }
        }
    }
}

// ---------------- launcher ----------------
extern "C" void kernel_launch(void* const* d_in, const int* in_sizes, int n_in,
                              void* d_out, int out_size)
{
    const int*   tokens = (const int*)  d_in[0];  // [32, 512] int32
    const float* state  = (const float*)d_in[1];  // [32, 256]
    const float* Wxh    = (const float*)d_in[2];  // [10000, 256]
    const float* Whh    = (const float*)d_in[3];  // [256, 256]
    const float* bh     = (const float*)d_in[4];  // [256]
    const float* Wd     = (const float*)d_in[5];  // [256, 10000]
    const float* bd     = (const float*)d_in[6];  // [10000]

    float* out  = (float*)d_out;                       // [16384, 10000]
    float* hfin = out + (size_t)MTOT * VOCAB;          // [32, 256]

    cudaFuncSetAttribute(rnn_kernel,
                         cudaFuncAttributeMaxDynamicSharedMemorySize, RNN_SMEM);
    cudaFuncSetAttribute(gemm_mma,
                         cudaFuncAttributeMaxDynamicSharedMemorySize, GSMEM);

    __nv_bfloat16 *yh, *yl, *wth, *wtl;
    cudaGetSymbolAddress((void**)&yh,  g_yh);
    cudaGetSymbolAddress((void**)&yl,  g_yl);
    cudaGetSymbolAddress((void**)&wth, g_wth);
    cudaGetSymbolAddress((void**)&wtl, g_wtl);

    rnn_kernel<<<BATCH, 256, RNN_SMEM>>>(tokens, state, Wxh, Whh, bh, hfin);

    dim3 tgrid((VOCAB + 31) / 32, HID / 32);           // (313, 8)
    wd_transpose_split<<<tgrid, dim3(32, 8)>>>(Wd);

    dim3 ggrid((VOCAB + GBN - 1) / GBN, MTOT / GBM);   // (79, 128)
    gemm_mma<<<ggrid, 256, GSMEM>>>(yh, yl, wth, wtl, bd, out);
}

// round 6
// speedup vs baseline: 2.0644x; 1.0543x over previous
#include <cuda_runtime.h>
#include <cuda_bf16.h>
#include <cstdint>

// Problem constants
#define VOCAB 10000
#define HID   256
#define BATCH 32
#define SEQL  512
#define MTOT  (SEQL * BATCH)   // 16384

typedef unsigned long long u64;

// ---------------- scratch (bf16 split operands) ----------------
__device__ __nv_bfloat16 g_yh[(size_t)MTOT * HID];    // Y hi  [M, K]
__device__ __nv_bfloat16 g_yl[(size_t)MTOT * HID];    // Y lo  [M, K]
__device__ __nv_bfloat16 g_wth[(size_t)VOCAB * HID];  // Wd^T hi [N, K]
__device__ __nv_bfloat16 g_wtl[(size_t)VOCAB * HID];  // Wd^T lo [N, K]

// ================= helpers =================
__device__ __forceinline__ uint32_t smem_u32(const void* p) {
    uint32_t a;
    asm("{ .reg .u64 t; cvta.to.shared.u64 t, %1; cvt.u32.u64 %0, t; }"
        : "=r"(a) : "l"(p));
    return a;
}
__device__ __forceinline__ void cpa16(uint32_t dst, const void* src, uint32_t sz) {
    asm volatile("cp.async.cg.shared.global [%0], [%1], 16, %2;"
                 :: "r"(dst), "l"(src), "r"(sz) : "memory");
}
__device__ __forceinline__ void ldm_x4(uint32_t* r, uint32_t addr) {
    asm volatile("ldmatrix.sync.aligned.m8n8.x4.shared.b16 {%0,%1,%2,%3}, [%4];"
                 : "=r"(r[0]), "=r"(r[1]), "=r"(r[2]), "=r"(r[3]) : "r"(addr));
}
__device__ __forceinline__ void mma_bf16(float* c, const uint32_t* a, const uint32_t* b) {
    asm volatile(
        "mma.sync.aligned.m16n8k16.row.col.f32.bf16.bf16.f32 "
        "{%0,%1,%2,%3}, {%4,%5,%6,%7}, {%8,%9}, {%0,%1,%2,%3};"
        : "+f"(c[0]), "+f"(c[1]), "+f"(c[2]), "+f"(c[3])
        : "r"(a[0]), "r"(a[1]), "r"(a[2]), "r"(a[3]), "r"(b[0]), "r"(b[1]));
}
__device__ __forceinline__ u64 packf2(float lo, float hi) {
    u64 d;
    asm("mov.b64 %0, {%1, %2};" : "=l"(d) : "f"(lo), "f"(hi));
    return d;
}
__device__ __forceinline__ void unpackf2(u64 d, float& lo, float& hi) {
    asm("mov.b64 {%0, %1}, %2;" : "=f"(lo), "=f"(hi) : "l"(d));
}
__device__ __forceinline__ u64 fma2(u64 a, u64 b, u64 c) {
    u64 d;
    asm("fma.rn.f32x2 %0, %1, %2, %3;" : "=l"(d) : "l"(a), "l"(b), "l"(c));
    return d;
}
// fast tanh: 1 - 2/(e^{2x}+1); saturates correctly at +-inf
__device__ __forceinline__ float fast_tanh(float x) {
    float z = __expf(2.0f * x);
    return 1.0f - __fdividef(2.0f, z + 1.0f);
}

// ---------------- Recurrence kernel (f32x2, 4 acc chains) ----
#define KREG 128
#define KSH  (HID - KREG)
#define KSHQ (KSH / 4)
#define RNN_SMEM (KSHQ * HID * 16)

__global__ void __launch_bounds__(256, 1)
rnn_kernel(const int* __restrict__ tokens, const float* __restrict__ state,
           const float* __restrict__ Wxh, const float* __restrict__ Whh,
           const float* __restrict__ bh, float* __restrict__ hfin)
{
    extern __shared__ float4 Wsh4[];                 // [KSHQ][HID] float4
    __shared__ __align__(16) float hbuf[2][HID];

    const int b = blockIdx.x;
    const int i = threadIdx.x;

    // Whh rows [0, KREG) for column i, packed as 64 f32x2 pairs
    u64 Wreg2[KREG / 2];
#pragma unroll
    for (int q = 0; q < KREG / 2; q++)
        Wreg2[q] = packf2(Whh[(2 * q) * HID + i], Whh[(2 * q + 1) * HID + i]);

    // Whh rows [KREG, 256) in shared as float4 per (kq, i)
    for (int kq = 0; kq < KSHQ; kq++) {
        float4 v;
        v.x = Whh[(KREG + 4 * kq + 0) * HID + i];
        v.y = Whh[(KREG + 4 * kq + 1) * HID + i];
        v.z = Whh[(KREG + 4 * kq + 2) * HID + i];
        v.w = Whh[(KREG + 4 * kq + 3) * HID + i];
        Wsh4[kq * HID + i] = v;
    }

    const float bias = bh[i];
    hbuf[0][i] = state[b * HID + i];
    __syncthreads();

    const int* toks = tokens + b * SEQL;
    float e = Wxh[toks[0] * HID + i];
    int cur = 0;

    for (int t = 0; t < SEQL; t++) {
        float e_next = (t + 1 < SEQL) ? Wxh[toks[t + 1] * HID + i] : 0.f;

        u64 acc[4];
        acc[0] = packf2(e + bias, 0.f);
        acc[1] = 0ull; acc[2] = 0ull; acc[3] = 0ull;

        const ulonglong2* h22 = (const ulonglong2*)hbuf[cur];

        // register part: k = 0 .. KREG-1
#pragma unroll
        for (int q = 0; q < KREG / 4; q++) {          // q: one float4 of h
            ulonglong2 hv = h22[q];
            acc[0] = fma2(hv.x, Wreg2[2 * q],     acc[0]);
            acc[1] = fma2(hv.y, Wreg2[2 * q + 1], acc[1]);
        }
        // shared part: k = KREG .. 255
#pragma unroll
        for (int kq = 0; kq < KSHQ; kq++) {
            ulonglong2 hv = h22[KREG / 4 + kq];
            float4 wv = Wsh4[kq * HID + i];
            const u64* wp = (const u64*)&wv;
            acc[2] = fma2(hv.x, wp[0], acc[2]);
            acc[3] = fma2(hv.y, wp[1], acc[3]);
        }

        float s0, s1, s2, s3, s4, s5, s6, s7;
        unpackf2(acc[0], s0, s1);
        unpackf2(acc[1], s2, s3);
        unpackf2(acc[2], s4, s5);
        unpackf2(acc[3], s6, s7);
        float sum = ((s0 + s2) + (s1 + s3)) + ((s4 + s6) + (s5 + s7));

        float hn = fast_tanh(sum);
        size_t oidx = ((size_t)t * BATCH + b) * HID + i;
        __nv_bfloat16 hh = __float2bfloat16(hn);
        g_yh[oidx] = hh;
        g_yl[oidx] = __float2bfloat16(hn - __bfloat162float(hh));
        hbuf[cur ^ 1][i] = hn;
        if (t == SEQL - 1) hfin[b * HID + i] = hn;
        __syncthreads();
        cur ^= 1;
        e = e_next;
    }
}

// ---------------- Wd transpose + bf16 split: [K,N] f32 -> [N,K] bf16 hi/lo --
__global__ void __launch_bounds__(256)
wd_transpose_split(const float* __restrict__ Wd)
{
    __shared__ float tile[32][33];
    const int tx = threadIdx.x;          // 0..31
    const int ty = threadIdx.y;          // 0..7
    const int n0 = blockIdx.x * 32;
    const int k0 = blockIdx.y * 32;

#pragma unroll
    for (int r = 0; r < 4; r++) {
        int k = k0 + ty + r * 8;
        int n = n0 + tx;
        tile[ty + r * 8][tx] = (n < VOCAB) ? Wd[(size_t)k * VOCAB + n] : 0.f;
    }
    __syncthreads();

#pragma unroll
    for (int r = 0; r < 4; r++) {
        int n = n0 + ty + r * 8;
        int k = k0 + tx;
        if (n < VOCAB) {
            float v = tile[tx][ty + r * 8];
            __nv_bfloat16 hi = __float2bfloat16(v);
            g_wth[(size_t)n * HID + k] = hi;
            g_wtl[(size_t)n * HID + k] = __float2bfloat16(v - __bfloat162float(hi));
        }
    }
}

// ---------------- mma.sync GEMM: C = (Yh+Yl) @ (Wth+Wtl)^T + bd --------------
// 128x128 CTA tile, 8 warps (2x4), 64x32 per warp. K chunks of 32 bf16,
// double-buffered cp.async. 3-pass bf16 split into shared fp32 accumulators.
// B is [N,K] K-contiguous -> B fragments load with NON-trans ldmatrix.
#define GBM 128
#define GBN 128
#define GBK 32
#define ROWB 80                            // bytes per smem row (32 bf16 + pad)
#define MATB (128 * ROWB)                  // 10240 B per matrix tile
#define STAGEB (4 * MATB)                  // Ah, Al, Bh, Bl
#define GSMEM (2 * STAGEB)                 // 81920 B

__global__ void __launch_bounds__(256, 2)
gemm_mma(const __nv_bfloat16* __restrict__ Yh, const __nv_bfloat16* __restrict__ Yl,
         const __nv_bfloat16* __restrict__ Bth, const __nv_bfloat16* __restrict__ Btl,
         const float* __restrict__ bd, float* __restrict__ C)
{
    extern __shared__ __align__(16) char smraw[];
    const uint32_t base = smem_u32(smraw);

    const int tid  = threadIdx.x;
    const int lane = tid & 31;
    const int wid  = tid >> 5;
    const int wm   = wid & 1;              // 0..1
    const int wn   = wid >> 1;             // 0..3
    const int m0   = blockIdx.y * GBM;
    const int n0   = blockIdx.x * GBN;

    float acc[4][4][4];
#pragma unroll
    for (int i = 0; i < 4; i++)
#pragma unroll
        for (int j = 0; j < 4; j++)
#pragma unroll
            for (int q = 0; q < 4; q++)
                acc[i][j][q] = 0.f;

    auto load_stage = [&](int st, int kc) {
        const uint32_t sb = base + st * STAGEB;
        const int kel = kc * GBK;
#pragma unroll
        for (int j = 0; j < 2; j++) {
            int u = tid + j * 256;
            int r = u >> 2;
            int sg = u & 3;
            uint32_t off = (uint32_t)r * ROWB + sg * 16;
            cpa16(sb + 0 * MATB + off, Yh + (size_t)(m0 + r) * HID + kel + sg * 8, 16);
            cpa16(sb + 1 * MATB + off, Yl + (size_t)(m0 + r) * HID + kel + sg * 8, 16);
            int nr = n0 + r;
            uint32_t ok = (nr < VOCAB) ? 16u : 0u;
            size_t br = (nr < VOCAB) ? (size_t)nr : 0;
            cpa16(sb + 2 * MATB + off, Bth + br * HID + kel + sg * 8, ok);
            cpa16(sb + 3 * MATB + off, Btl + br * HID + kel + sg * 8, ok);
        }
        asm volatile("cp.async.commit_group;" ::: "memory");
    };

    load_stage(0, 0);

    const int NKC = HID / GBK;             // 8 chunks
    for (int kc = 0; kc < NKC; kc++) {
        if (kc + 1 < NKC) {
            load_stage((kc + 1) & 1, kc + 1);
            asm volatile("cp.async.wait_group 1;" ::: "memory");
        } else {
            asm volatile("cp.async.wait_group 0;" ::: "memory");
        }
        __syncthreads();

        const uint32_t sb = base + (kc & 1) * STAGEB;
        const uint32_t Ah = sb, Al = sb + MATB, Bh = sb + 2 * MATB, Bl = sb + 3 * MATB;

#pragma unroll
        for (int ks = 0; ks < 2; ks++) {
            const int k0 = ks * 16;
            uint32_t bh[2][4], bl[2][4];
#pragma unroll
            for (int h = 0; h < 2; h++) {
                int row = wn * 32 + h * 16 + ((lane >> 4) & 1) * 8 + (lane & 7);
                int col = k0 + ((lane >> 3) & 1) * 8;
                uint32_t off = (uint32_t)row * ROWB + col * 2;
                ldm_x4(bh[h], Bh + off);
                ldm_x4(bl[h], Bl + off);
            }
#pragma unroll
            for (int mi = 0; mi < 4; mi++) {
                int rowA = wm * 64 + mi * 16 + (lane & 15);
                int colA = k0 + (lane >> 4) * 8;
                uint32_t offA = (uint32_t)rowA * ROWB + colA * 2;
                uint32_t ah[4], al[4];
                ldm_x4(ah, Ah + offA);
                ldm_x4(al, Al + offA);
#pragma unroll
                for (int ni = 0; ni < 4; ni++) {
                    const uint32_t* ph = &bh[ni >> 1][(ni & 1) * 2];
                    const uint32_t* pl = &bl[ni >> 1][(ni & 1) * 2];
                    mma_bf16(acc[mi][ni], ah, ph);   // Ah * Bh
                    mma_bf16(acc[mi][ni], ah, pl);   // Ah * Bl
                    mma_bf16(acc[mi][ni], al, ph);   // Al * Bh
                }
            }
        }
        __syncthreads();
    }

    // ---- epilogue: bias + store ----
    const int g  = lane >> 2;
    const int tq = lane & 3;
#pragma unroll
    for (int mi = 0; mi < 4; mi++) {
        int r0 = m0 + wm * 64 + mi * 16 + g;
#pragma unroll
        for (int ni = 0; ni < 4; ni++) {
            int col = n0 + wn * 32 + ni * 8 + tq * 2;
            if (col < VOCAB) {
                float b0 = bd[col], b1 = bd[col + 1];
                float2 v0 = { acc[mi][ni][0] + b0, acc[mi][ni][1] + b1 };
                float2 v1 = { acc[mi][ni][2] + b0, acc[mi][ni][3] + b1 };
                *(float2*)(C + (size_t)r0 * VOCAB + col) = v0;
                *(float2*)(C + (size_t)(r0 + 8) * VOCAB + col) = v1;
            }
        }
    }
}

// ---------------- launcher ----------------
extern "C" void kernel_launch(void* const* d_in, const int* in_sizes, int n_in,
                              void* d_out, int out_size)
{
    const int*   tokens = (const int*)  d_in[0];  // [32, 512] int32
    const float* state  = (const float*)d_in[1];  // [32, 256]
    const float* Wxh    = (const float*)d_in[2];  // [10000, 256]
    const float* Whh    = (const float*)d_in[3];  // [256, 256]
    const float* bh     = (const float*)d_in[4];  // [256]
    const float* Wd     = (const float*)d_in[5];  // [256, 10000]
    const float* bd     = (const float*)d_in[6];  // [10000]

    float* out  = (float*)d_out;                       // [16384, 10000]
    float* hfin = out + (size_t)MTOT * VOCAB;          // [32, 256]

    cudaFuncSetAttribute(rnn_kernel,
                         cudaFuncAttributeMaxDynamicSharedMemorySize, RNN_SMEM);
    cudaFuncSetAttribute(gemm_mma,
                         cudaFuncAttributeMaxDynamicSharedMemorySize, GSMEM);

    __nv_bfloat16 *yh, *yl, *wth, *wtl;
    cudaGetSymbolAddress((void**)&yh,  g_yh);
    cudaGetSymbolAddress((void**)&yl,  g_yl);
    cudaGetSymbolAddress((void**)&wth, g_wth);
    cudaGetSymbolAddress((void**)&wtl, g_wtl);

    rnn_kernel<<<BATCH, 256, RNN_SMEM>>>(tokens, state, Wxh, Whh, bh, hfin);

    dim3 tgrid((VOCAB + 31) / 32, HID / 32);           // (313, 8)
    wd_transpose_split<<<tgrid, dim3(32, 8)>>>(Wd);

    dim3 ggrid((VOCAB + GBN - 1) / GBN, MTOT / GBM);   // (79, 128)
    gemm_mma<<<ggrid, 256, GSMEM>>>(yh, yl, wth, wtl, bd, out);
}